// round 1
// baseline (speedup 1.0000x reference)
#include <cuda_runtime.h>
#include <math.h>

#define T_TOK 16384
#define DIMN  1024
#define HIDN  2048
#define NE    8

#define BM 64
#define BN 64
#define BK 16

// ---- device scratch (static __device__ arrays are the sanctioned scratch path) ----
__device__ int   g_count[NE];
__device__ int   g_tok[NE * T_TOK];            // token id per (expert, pos)
__device__ float g_wt [NE * T_TOK];            // routing weight per flat slot
__device__ int   g_slot[T_TOK * 2];            // per token: its 2 flat slots
__device__ float g_H[(size_t)NE * T_TOK * HIDN];   // hidden activations (capacity-indexed)
__device__ float g_P[(size_t)NE * T_TOK * DIMN];   // per-assignment partial outputs

// ---------------------------------------------------------------------------
__global__ void reset_kernel() {
    if (threadIdx.x < NE) g_count[threadIdx.x] = 0;
}

// ---------------------------------------------------------------------------
// Gating: one warp per token. logits = x[t] . wg[:,e], top-2, softmax-of-2,
// atomic append into per-expert lists.
__global__ void gate_kernel(const float* __restrict__ x, const float* __restrict__ wg) {
    int warp = threadIdx.x >> 5;
    int lane = threadIdx.x & 31;
    int t = blockIdx.x * 8 + warp;
    if (t >= T_TOK) return;

    float acc[NE];
#pragma unroll
    for (int e = 0; e < NE; e++) acc[e] = 0.f;

    const float* xr = x + (size_t)t * DIMN;
    for (int d = lane; d < DIMN; d += 32) {
        float xv = xr[d];
#pragma unroll
        for (int e = 0; e < NE; e++) acc[e] += xv * wg[d * NE + e];
    }
#pragma unroll
    for (int e = 0; e < NE; e++) {
#pragma unroll
        for (int o = 16; o > 0; o >>= 1)
            acc[e] += __shfl_xor_sync(0xffffffffu, acc[e], o);
    }

    if (lane == 0) {
        int i0 = 0; float l0 = acc[0];
#pragma unroll
        for (int e = 1; e < NE; e++) if (acc[e] > l0) { l0 = acc[e]; i0 = e; }
        int i1 = -1; float l1 = -3.0e38f;
#pragma unroll
        for (int e = 0; e < NE; e++) if (e != i0 && acc[e] > l1) { l1 = acc[e]; i1 = e; }

        float w0 = 1.f / (1.f + expf(l1 - l0));   // softmax over the top-2
        float w1v = 1.f - w0;

        int p0 = atomicAdd(&g_count[i0], 1);
        g_tok[i0 * T_TOK + p0] = t;
        g_wt [i0 * T_TOK + p0] = w0;
        g_slot[2 * t + 0] = i0 * T_TOK + p0;

        int p1 = atomicAdd(&g_count[i1], 1);
        g_tok[i1 * T_TOK + p1] = t;
        g_wt [i1 * T_TOK + p1] = w1v;
        g_slot[2 * t + 1] = i1 * T_TOK + p1;
    }
}

// ---------------------------------------------------------------------------
// FFN stage 1 (grouped, gathered): H = silu(X w1^T) * (X w3^T) per expert.
// A: gathered token rows [BM x BK]; B: w1/w3 rows (hidden units) [BN x BK].
// C[m,n] = sum_k A[m,k] * B[n,k]  (NT GEMM, both row-major over DIM)
__global__ void ffn1_kernel(const float* __restrict__ x,
                            const float* __restrict__ w1,
                            const float* __restrict__ w3) {
    int e   = blockIdx.z;
    int cnt = g_count[e];
    int m0  = blockIdx.y * BM;
    if (m0 >= cnt) return;
    int n0  = blockIdx.x * BN;

    __shared__ float As [BM][BK + 1];
    __shared__ float B1s[BN][BK + 1];
    __shared__ float B3s[BN][BK + 1];
    __shared__ int   toks[BM];

    int tid = threadIdx.x;                 // 256 threads
    if (tid < BM) {
        int row = m0 + tid;
        toks[tid] = (row < cnt) ? g_tok[e * T_TOK + row] : -1;
    }
    __syncthreads();

    const float* w1p = w1 + (size_t)e * HIDN * DIMN;
    const float* w3p = w3 + (size_t)e * HIDN * DIMN;

    int tx = tid & 15, ty = tid >> 4;
    int lr = tid >> 2;           // 0..63 : row within tile for loads
    int lc = (tid & 3) * 4;      // 0,4,8,12 : k-offset for float4 load
    int myTok = toks[lr];

    float acc1[4][4], acc3[4][4];
#pragma unroll
    for (int i = 0; i < 4; i++)
#pragma unroll
        for (int j = 0; j < 4; j++) { acc1[i][j] = 0.f; acc3[i][j] = 0.f; }

    for (int k0 = 0; k0 < DIMN; k0 += BK) {
        float4 av = make_float4(0.f, 0.f, 0.f, 0.f);
        if (myTok >= 0)
            av = *reinterpret_cast<const float4*>(&x[(size_t)myTok * DIMN + k0 + lc]);
        As[lr][lc + 0] = av.x; As[lr][lc + 1] = av.y;
        As[lr][lc + 2] = av.z; As[lr][lc + 3] = av.w;

        float4 b1 = *reinterpret_cast<const float4*>(&w1p[(size_t)(n0 + lr) * DIMN + k0 + lc]);
        B1s[lr][lc + 0] = b1.x; B1s[lr][lc + 1] = b1.y;
        B1s[lr][lc + 2] = b1.z; B1s[lr][lc + 3] = b1.w;

        float4 b3 = *reinterpret_cast<const float4*>(&w3p[(size_t)(n0 + lr) * DIMN + k0 + lc]);
        B3s[lr][lc + 0] = b3.x; B3s[lr][lc + 1] = b3.y;
        B3s[lr][lc + 2] = b3.z; B3s[lr][lc + 3] = b3.w;
        __syncthreads();

#pragma unroll
        for (int kk = 0; kk < BK; kk++) {
            float a[4], br1[4], br3[4];
#pragma unroll
            for (int i = 0; i < 4; i++) a[i]   = As [ty * 4 + i][kk];
#pragma unroll
            for (int j = 0; j < 4; j++) br1[j] = B1s[tx * 4 + j][kk];
#pragma unroll
            for (int j = 0; j < 4; j++) br3[j] = B3s[tx * 4 + j][kk];
#pragma unroll
            for (int i = 0; i < 4; i++)
#pragma unroll
                for (int j = 0; j < 4; j++) {
                    acc1[i][j] += a[i] * br1[j];
                    acc3[i][j] += a[i] * br3[j];
                }
        }
        __syncthreads();
    }

    // epilogue: h = silu(h1) * h3
#pragma unroll
    for (int i = 0; i < 4; i++) {
        int row = m0 + ty * 4 + i;
        if (row < cnt) {
            float* hp = &g_H[(size_t)(e * T_TOK + row) * HIDN + n0 + tx * 4];
#pragma unroll
            for (int j = 0; j < 4; j++) {
                float z = acc1[i][j];
                float s = z / (1.f + expf(-z));
                hp[j] = s * acc3[i][j];
            }
        }
    }
}

// ---------------------------------------------------------------------------
// FFN stage 2 (grouped): P = H w2  (NN GEMM: C[m,n] = sum_k A[m,k] * B[k,n])
__global__ void ffn2_kernel(const float* __restrict__ w2) {
    int e   = blockIdx.z;
    int cnt = g_count[e];
    int m0  = blockIdx.y * BM;
    if (m0 >= cnt) return;
    int n0  = blockIdx.x * BN;

    __shared__ float As[BM][BK + 1];
    __shared__ float Bs[BK][BN];

    int tid = threadIdx.x;
    int tx = tid & 15, ty = tid >> 4;

    const float* w2p = w2 + (size_t)e * HIDN * DIMN;
    const float* Hp  = &g_H[(size_t)(e * T_TOK) * HIDN];

    // A-load mapping (64x16): tid -> row tid/4, k-offset (tid%4)*4
    int alr = tid >> 2;
    int alc = (tid & 3) * 4;
    bool arow_ok = (m0 + alr) < cnt;
    // B-load mapping (16x64): tid -> k-row tid/16, n-offset (tid%16)*4
    int blr = tid >> 4;
    int blc = (tid & 15) * 4;

    float acc[4][4];
#pragma unroll
    for (int i = 0; i < 4; i++)
#pragma unroll
        for (int j = 0; j < 4; j++) acc[i][j] = 0.f;

    for (int k0 = 0; k0 < HIDN; k0 += BK) {
        float4 av = make_float4(0.f, 0.f, 0.f, 0.f);
        if (arow_ok)
            av = *reinterpret_cast<const float4*>(&Hp[(size_t)(m0 + alr) * HIDN + k0 + alc]);
        As[alr][alc + 0] = av.x; As[alr][alc + 1] = av.y;
        As[alr][alc + 2] = av.z; As[alr][alc + 3] = av.w;

        float4 bv = *reinterpret_cast<const float4*>(&w2p[(size_t)(k0 + blr) * DIMN + n0 + blc]);
        *reinterpret_cast<float4*>(&Bs[blr][blc]) = bv;
        __syncthreads();

#pragma unroll
        for (int kk = 0; kk < BK; kk++) {
            float a[4];
#pragma unroll
            for (int i = 0; i < 4; i++) a[i] = As[ty * 4 + i][kk];
            float4 bv4 = *reinterpret_cast<const float4*>(&Bs[kk][tx * 4]);
            float b[4] = {bv4.x, bv4.y, bv4.z, bv4.w};
#pragma unroll
            for (int i = 0; i < 4; i++)
#pragma unroll
                for (int j = 0; j < 4; j++) acc[i][j] += a[i] * b[j];
        }
        __syncthreads();
    }

#pragma unroll
    for (int i = 0; i < 4; i++) {
        int row = m0 + ty * 4 + i;
        if (row < cnt) {
            float* pp = &g_P[(size_t)(e * T_TOK + row) * DIMN + n0 + tx * 4];
#pragma unroll
            for (int j = 0; j < 4; j++) pp[j] = acc[i][j];
        }
    }
}

// ---------------------------------------------------------------------------
// Combine: y[t] = w0 * P[slot0] + w1 * P[slot1]   (deterministic, no atomics)
__global__ void combine_kernel(float* __restrict__ y) {
    size_t idx = (size_t)blockIdx.x * blockDim.x + threadIdx.x;   // over T*DIM/4
    if (idx >= (size_t)T_TOK * DIMN / 4) return;
    int t  = (int)(idx / (DIMN / 4));
    int d4 = (int)(idx % (DIMN / 4)) * 4;

    int s0 = g_slot[2 * t + 0];
    int s1 = g_slot[2 * t + 1];
    float w0 = g_wt[s0];
    float w1 = g_wt[s1];

    float4 p0 = *reinterpret_cast<const float4*>(&g_P[(size_t)s0 * DIMN + d4]);
    float4 p1 = *reinterpret_cast<const float4*>(&g_P[(size_t)s1 * DIMN + d4]);
    float4 r;
    r.x = w0 * p0.x + w1 * p1.x;
    r.y = w0 * p0.y + w1 * p1.y;
    r.z = w0 * p0.z + w1 * p1.z;
    r.w = w0 * p0.w + w1 * p1.w;
    *reinterpret_cast<float4*>(&y[(size_t)t * DIMN + d4]) = r;
}

// ---------------------------------------------------------------------------
extern "C" void kernel_launch(void* const* d_in, const int* in_sizes, int n_in,
                              void* d_out, int out_size) {
    const float* x  = (const float*)d_in[0];
    const float* wg = (const float*)d_in[1];
    const float* w1 = (const float*)d_in[2];
    const float* w2 = (const float*)d_in[3];
    const float* w3 = (const float*)d_in[4];
    float* y = (float*)d_out;

    reset_kernel<<<1, 32>>>();
    gate_kernel<<<T_TOK / 8, 256>>>(x, wg);
    ffn1_kernel<<<dim3(HIDN / BN, T_TOK / BM, NE), 256>>>(x, w1, w3);
    ffn2_kernel<<<dim3(DIMN / BN, T_TOK / BM, NE), 256>>>(w2);
    combine_kernel<<<(T_TOK * DIMN / 4 + 255) / 256, 256>>>(y);
}

// round 4
// speedup vs baseline: 3.2224x; 3.2224x over previous
#include <cuda_runtime.h>
#include <cstdint>
#include <math.h>

#define T_TOK 16384
#define DIMN  1024
#define HIDN  2048
#define NE    8
#define NA    (2*T_TOK)

#define BK    16
#define PADA  20    // row stride (floats) for A / NT-B tiles
#define PADB  136   // row stride (floats) for ffn2 B tile [16][128]

// ============================ helpers ============================
#define CP_ASYNC16(dst, src) asm volatile("cp.async.cg.shared.global [%0], [%1], 16;" :: "r"(dst), "l"(src))
#define CP_COMMIT()          asm volatile("cp.async.commit_group;" ::: "memory")
#define CP_WAIT(n)           asm volatile("cp.async.wait_group %0;" :: "n"(n) : "memory")

__device__ __forceinline__ uint32_t smem_u32(const void* p) {
    uint32_t a;
    asm("{ .reg .u64 t; cvta.to.shared.u64 t, %1; cvt.u32.u64 %0, t; }" : "=r"(a) : "l"(p));
    return a;
}
__device__ __forceinline__ float tf32r(float x) {
    uint32_t u; asm("cvt.rna.tf32.f32 %0, %1;" : "=r"(u) : "f"(x)); return __uint_as_float(u);
}
__device__ __forceinline__ void mma_tf32(float* c, const uint32_t* a, const uint32_t* b) {
    asm volatile(
        "mma.sync.aligned.m16n8k8.row.col.f32.tf32.tf32.f32 "
        "{%0,%1,%2,%3}, {%4,%5,%6,%7}, {%8,%9}, {%0,%1,%2,%3};"
        : "+f"(c[0]), "+f"(c[1]), "+f"(c[2]), "+f"(c[3])
        : "r"(a[0]), "r"(a[1]), "r"(a[2]), "r"(a[3]), "r"(b[0]), "r"(b[1]));
}

// ============================ device scratch ============================
__device__ int   g_count[NE];
__device__ int   g_count2[NE];
__device__ int   g_off[NE];
__device__ int   g_choice[T_TOK * 2];
__device__ float g_cw[T_TOK * 2];
__device__ int   g_tokOf[NA];
__device__ float g_wt[NA];
__device__ int   g_slot[T_TOK * 2];
__device__ float g_Xg[(size_t)NA * DIMN];          // gathered tokens, tf32-rounded
__device__ float g_Ht[(size_t)NA * HIDN];          // hidden, tf32-rounded
__device__ float g_P [(size_t)NA * DIMN];          // per-assignment partials
__device__ float g_w1t[(size_t)NE * HIDN * DIMN];  // tf32-rounded
__device__ float g_w3t[(size_t)NE * HIDN * DIMN];
__device__ float g_w2r[(size_t)NE * HIDN * DIMN];  // tf32-rounded (same layout as w2)

// ============================ small kernels ============================
__global__ void reset_kernel() {
    if (threadIdx.x < NE) { g_count[threadIdx.x] = 0; g_count2[threadIdx.x] = 0; }
}

__global__ void gate_kernel(const float* __restrict__ x, const float* __restrict__ wg) {
    int warp = threadIdx.x >> 5, lane = threadIdx.x & 31;
    int t = blockIdx.x * 8 + warp;
    if (t >= T_TOK) return;
    float acc[NE];
#pragma unroll
    for (int e = 0; e < NE; e++) acc[e] = 0.f;
    const float* xr = x + (size_t)t * DIMN;
    for (int d = lane; d < DIMN; d += 32) {
        float xv = xr[d];
#pragma unroll
        for (int e = 0; e < NE; e++) acc[e] += xv * wg[d * NE + e];
    }
#pragma unroll
    for (int e = 0; e < NE; e++)
#pragma unroll
        for (int o = 16; o > 0; o >>= 1) acc[e] += __shfl_xor_sync(0xffffffffu, acc[e], o);
    if (lane == 0) {
        int i0 = 0; float l0 = acc[0];
#pragma unroll
        for (int e = 1; e < NE; e++) if (acc[e] > l0) { l0 = acc[e]; i0 = e; }
        int i1 = -1; float l1 = -3.0e38f;
#pragma unroll
        for (int e = 0; e < NE; e++) if (e != i0 && acc[e] > l1) { l1 = acc[e]; i1 = e; }
        float w0 = 1.f / (1.f + expf(l1 - l0));
        g_choice[2 * t] = i0;  g_choice[2 * t + 1] = i1;
        g_cw[2 * t] = w0;      g_cw[2 * t + 1] = 1.f - w0;
        atomicAdd(&g_count[i0], 1);
        atomicAdd(&g_count[i1], 1);
    }
}

__global__ void scan_kernel() {
    if (threadIdx.x == 0) {
        int off = 0;
        for (int e = 0; e < NE; e++) { g_off[e] = off; off += g_count[e]; }
    }
}

__global__ void build_kernel() {
    int t = blockIdx.x * blockDim.x + threadIdx.x;
    if (t >= T_TOK) return;
#pragma unroll
    for (int j = 0; j < 2; j++) {
        int e = g_choice[2 * t + j];
        int p = atomicAdd(&g_count2[e], 1);
        int s = g_off[e] + p;
        g_tokOf[s] = t;
        g_wt[s] = g_cw[2 * t + j];
        g_slot[2 * t + j] = s;
    }
}

__global__ void gather_kernel(const float* __restrict__ x) {
    size_t idx = (size_t)blockIdx.x * blockDim.x + threadIdx.x;
    if (idx >= (size_t)NA * (DIMN / 4)) return;
    int row = (int)(idx / (DIMN / 4));
    int c4 = (int)(idx % (DIMN / 4)) * 4;
    int tok = g_tokOf[row];
    float4 v = *reinterpret_cast<const float4*>(&x[(size_t)tok * DIMN + c4]);
    v.x = tf32r(v.x); v.y = tf32r(v.y); v.z = tf32r(v.z); v.w = tf32r(v.w);
    *reinterpret_cast<float4*>(&g_Xg[(size_t)row * DIMN + c4]) = v;
}

__global__ void convw_kernel(const float* __restrict__ w1, const float* __restrict__ w2,
                             const float* __restrict__ w3) {
    size_t idx = (size_t)blockIdx.x * blockDim.x + threadIdx.x;
    if (idx >= (size_t)NE * HIDN * DIMN / 4) return;
    size_t o = idx * 4;
    float4 a = *reinterpret_cast<const float4*>(&w1[o]);
    a.x = tf32r(a.x); a.y = tf32r(a.y); a.z = tf32r(a.z); a.w = tf32r(a.w);
    *reinterpret_cast<float4*>(&g_w1t[o]) = a;
    float4 b = *reinterpret_cast<const float4*>(&w3[o]);
    b.x = tf32r(b.x); b.y = tf32r(b.y); b.z = tf32r(b.z); b.w = tf32r(b.w);
    *reinterpret_cast<float4*>(&g_w3t[o]) = b;
    float4 c = *reinterpret_cast<const float4*>(&w2[o]);
    c.x = tf32r(c.x); c.y = tf32r(c.y); c.z = tf32r(c.z); c.w = tf32r(c.w);
    *reinterpret_cast<float4*>(&g_w2r[o]) = c;
}

// ============================ ffn1: H = silu(Xg W1^T) * (Xg W3^T) ============================
// BM=128 BN=64 BK=16. 256 threads, 8 warps as 4(m) x 2(n); warp tile 32x32.
__global__ void __launch_bounds__(256, 2) ffn1_kernel() {
    int e = blockIdx.z;
    int cnt = g_count[e];
    int mb = blockIdx.y;
    if (mb * 128 >= cnt) return;
    int base = g_off[e] + mb * 128;
    int n0 = blockIdx.x * 64;

    __shared__ float As [2][128 * PADA];
    __shared__ float B1s[2][64 * PADA];
    __shared__ float B3s[2][64 * PADA];

    int tid = threadIdx.x, wid = tid >> 5, lane = tid & 31;
    int wm = wid & 3, wn = wid >> 2;

    // A tile loads: each thread owns 8 contiguous floats of one row:
    // row = tid>>1, col base = (tid&1)*8; two 16B chunks at +0 and +4 floats.
    int arowL = tid >> 1;                   // 0..127
    int acol = (tid & 1) * 8;               // 0 or 8
    int arow = base + arowL; if (arow >= NA) arow = NA - 1;
    const float* srcA = g_Xg + (size_t)arow * DIMN + acol;
    uint32_t dstA = smem_u32(&As[0][arowL * PADA + acol]);

    int browL = tid >> 2;                   // 0..63
    int bcol = (tid & 3) * 4;               // 0,4,8,12
    const float* srcB1 = g_w1t + ((size_t)e * HIDN + n0 + browL) * DIMN + bcol;
    const float* srcB3 = g_w3t + ((size_t)e * HIDN + n0 + browL) * DIMN + bcol;
    uint32_t dstB1 = smem_u32(&B1s[0][browL * PADA + bcol]);
    uint32_t dstB3 = smem_u32(&B3s[0][browL * PADA + bcol]);

    const uint32_t stA  = (uint32_t)(128 * PADA * 4);
    const uint32_t stB  = (uint32_t)(64 * PADA * 4);

    float acc1[2][4][4], acc3[2][4][4];
#pragma unroll
    for (int i = 0; i < 2; i++)
#pragma unroll
        for (int j = 0; j < 4; j++)
#pragma unroll
            for (int v = 0; v < 4; v++) { acc1[i][j][v] = 0.f; acc3[i][j][v] = 0.f; }

    // prefetch stage 0
    {
        CP_ASYNC16(dstA, srcA); CP_ASYNC16(dstA + 16, srcA + 4);
        CP_ASYNC16(dstB1, srcB1); CP_ASYNC16(dstB3, srcB3);
        CP_COMMIT();
    }

    const int KT = DIMN / BK;   // 64
    for (int kt = 0; kt < KT; kt++) {
        int cur = kt & 1;
        if (kt + 1 < KT) {
            int nx = (kt + 1) & 1;
            const float* sA = srcA + (kt + 1) * BK;
            const float* s1 = srcB1 + (kt + 1) * BK;
            const float* s3 = srcB3 + (kt + 1) * BK;
            CP_ASYNC16(dstA + nx * stA, sA); CP_ASYNC16(dstA + nx * stA + 16, sA + 4);
            CP_ASYNC16(dstB1 + nx * stB, s1); CP_ASYNC16(dstB3 + nx * stB, s3);
            CP_COMMIT();
            CP_WAIT(1);
        } else {
            CP_WAIT(0);
        }
        __syncthreads();

        const float* A = As[cur];
        const float* B1 = B1s[cur];
        const float* B3 = B3s[cur];
#pragma unroll
        for (int kk = 0; kk < 2; kk++) {
            int k0 = kk * 8;
            uint32_t a[2][4];
#pragma unroll
            for (int i = 0; i < 2; i++) {
                int r = wm * 32 + i * 16 + (lane >> 2);
                int c = k0 + (lane & 3);
                a[i][0] = __float_as_uint(A[r * PADA + c]);
                a[i][1] = __float_as_uint(A[(r + 8) * PADA + c]);
                a[i][2] = __float_as_uint(A[r * PADA + c + 4]);
                a[i][3] = __float_as_uint(A[(r + 8) * PADA + c + 4]);
            }
            uint32_t b1[4][2], b3[4][2];
#pragma unroll
            for (int j = 0; j < 4; j++) {
                int n = wn * 32 + j * 8 + (lane >> 2);
                int c = k0 + (lane & 3);
                b1[j][0] = __float_as_uint(B1[n * PADA + c]);
                b1[j][1] = __float_as_uint(B1[n * PADA + c + 4]);
                b3[j][0] = __float_as_uint(B3[n * PADA + c]);
                b3[j][1] = __float_as_uint(B3[n * PADA + c + 4]);
            }
#pragma unroll
            for (int i = 0; i < 2; i++)
#pragma unroll
                for (int j = 0; j < 4; j++) {
                    mma_tf32(acc1[i][j], a[i], b1[j]);
                    mma_tf32(acc3[i][j], a[i], b3[j]);
                }
        }
        __syncthreads();
    }

    // epilogue: h = silu(z1)*z3, tf32-round, store
#pragma unroll
    for (int i = 0; i < 2; i++) {
#pragma unroll
        for (int half = 0; half < 2; half++) {
            int rloc = wm * 32 + i * 16 + (lane >> 2) + half * 8;
            if (mb * 128 + rloc < cnt) {
                float* hrow = g_Ht + (size_t)(base + rloc) * HIDN + n0;
#pragma unroll
                for (int j = 0; j < 4; j++) {
                    int cl = wn * 32 + j * 8 + (lane & 3) * 2;
                    float z0 = acc1[i][j][half * 2 + 0];
                    float z1 = acc1[i][j][half * 2 + 1];
                    float h0 = tf32r(z0 / (1.f + __expf(-z0)) * acc3[i][j][half * 2 + 0]);
                    float h1 = tf32r(z1 / (1.f + __expf(-z1)) * acc3[i][j][half * 2 + 1]);
                    *reinterpret_cast<float2*>(&hrow[cl]) = make_float2(h0, h1);
                }
            }
        }
    }
}

// ============================ ffn2: P = H W2 ============================
// BM=128 BN=128 BK=16. 256 threads, 8 warps as 4(m) x 2(n); warp tile 32x64.
__global__ void __launch_bounds__(256, 2) ffn2_kernel() {
    int e = blockIdx.z;
    int cnt = g_count[e];
    int mb = blockIdx.y;
    if (mb * 128 >= cnt) return;
    int base = g_off[e] + mb * 128;
    int n0 = blockIdx.x * 128;

    __shared__ float As[2][128 * PADA];
    __shared__ float Bs[2][16 * PADB];

    int tid = threadIdx.x, wid = tid >> 5, lane = tid & 31;
    int wm = wid & 3, wn = wid >> 2;

    int arowL = tid >> 1;
    int acol = (tid & 1) * 8;
    int arow = base + arowL; if (arow >= NA) arow = NA - 1;
    const float* srcA = g_Ht + (size_t)arow * HIDN + acol;
    uint32_t dstA = smem_u32(&As[0][arowL * PADA + acol]);

    // B: 16 rows x 128 floats; tid -> row=tid>>4 (0..15), col base=(tid&15)*8
    int browL = tid >> 4;
    int bcol = (tid & 15) * 8;
    const float* srcB = g_w2r + ((size_t)e * HIDN + browL) * DIMN + n0 + bcol;
    uint32_t dstB = smem_u32(&Bs[0][browL * PADB + bcol]);

    const uint32_t stA = (uint32_t)(128 * PADA * 4);
    const uint32_t stB = (uint32_t)(16 * PADB * 4);

    float acc[2][8][4];
#pragma unroll
    for (int i = 0; i < 2; i++)
#pragma unroll
        for (int j = 0; j < 8; j++)
#pragma unroll
            for (int v = 0; v < 4; v++) acc[i][j][v] = 0.f;

    {
        CP_ASYNC16(dstA, srcA); CP_ASYNC16(dstA + 16, srcA + 4);
        CP_ASYNC16(dstB, srcB); CP_ASYNC16(dstB + 16, srcB + 4);
        CP_COMMIT();
    }

    const int KT = HIDN / BK;   // 128
    for (int kt = 0; kt < KT; kt++) {
        int cur = kt & 1;
        if (kt + 1 < KT) {
            int nx = (kt + 1) & 1;
            const float* sA = srcA + (kt + 1) * BK;
            const float* sB = srcB + (size_t)(kt + 1) * BK * DIMN;
            CP_ASYNC16(dstA + nx * stA, sA); CP_ASYNC16(dstA + nx * stA + 16, sA + 4);
            CP_ASYNC16(dstB + nx * stB, sB); CP_ASYNC16(dstB + nx * stB + 16, sB + 4);
            CP_COMMIT();
            CP_WAIT(1);
        } else {
            CP_WAIT(0);
        }
        __syncthreads();

        const float* A = As[cur];
        const float* B = Bs[cur];
#pragma unroll
        for (int kk = 0; kk < 2; kk++) {
            int k0 = kk * 8;
            uint32_t a[2][4];
#pragma unroll
            for (int i = 0; i < 2; i++) {
                int r = wm * 32 + i * 16 + (lane >> 2);
                int c = k0 + (lane & 3);
                a[i][0] = __float_as_uint(A[r * PADA + c]);
                a[i][1] = __float_as_uint(A[(r + 8) * PADA + c]);
                a[i][2] = __float_as_uint(A[r * PADA + c + 4]);
                a[i][3] = __float_as_uint(A[(r + 8) * PADA + c + 4]);
            }
            uint32_t b[8][2];
#pragma unroll
            for (int j = 0; j < 8; j++) {
                int n = wn * 64 + j * 8 + (lane >> 2);
                int k = k0 + (lane & 3);
                b[j][0] = __float_as_uint(B[k * PADB + n]);
                b[j][1] = __float_as_uint(B[(k + 4) * PADB + n]);
            }
#pragma unroll
            for (int i = 0; i < 2; i++)
#pragma unroll
                for (int j = 0; j < 8; j++)
                    mma_tf32(acc[i][j], a[i], b[j]);
        }
        __syncthreads();
    }

#pragma unroll
    for (int i = 0; i < 2; i++) {
#pragma unroll
        for (int half = 0; half < 2; half++) {
            int rloc = wm * 32 + i * 16 + (lane >> 2) + half * 8;
            if (mb * 128 + rloc < cnt) {
                float* prow = g_P + (size_t)(base + rloc) * DIMN + n0;
#pragma unroll
                for (int j = 0; j < 8; j++) {
                    int cl = wn * 64 + j * 8 + (lane & 3) * 2;
                    *reinterpret_cast<float2*>(&prow[cl]) =
                        make_float2(acc[i][j][half * 2 + 0], acc[i][j][half * 2 + 1]);
                }
            }
        }
    }
}

// ============================ combine ============================
__global__ void combine_kernel(float* __restrict__ y) {
    size_t idx = (size_t)blockIdx.x * blockDim.x + threadIdx.x;
    if (idx >= (size_t)T_TOK * DIMN / 4) return;
    int t = (int)(idx / (DIMN / 4));
    int d4 = (int)(idx % (DIMN / 4)) * 4;
    int s0 = g_slot[2 * t], s1 = g_slot[2 * t + 1];
    float w0 = g_wt[s0], w1 = g_wt[s1];
    float4 p0 = *reinterpret_cast<const float4*>(&g_P[(size_t)s0 * DIMN + d4]);
    float4 p1 = *reinterpret_cast<const float4*>(&g_P[(size_t)s1 * DIMN + d4]);
    float4 r;
    r.x = w0 * p0.x + w1 * p1.x;
    r.y = w0 * p0.y + w1 * p1.y;
    r.z = w0 * p0.z + w1 * p1.z;
    r.w = w0 * p0.w + w1 * p1.w;
    *reinterpret_cast<float4*>(&y[(size_t)t * DIMN + d4]) = r;
}

// ============================ launch ============================
extern "C" void kernel_launch(void* const* d_in, const int* in_sizes, int n_in,
                              void* d_out, int out_size) {
    const float* x  = (const float*)d_in[0];
    const float* wg = (const float*)d_in[1];
    const float* w1 = (const float*)d_in[2];
    const float* w2 = (const float*)d_in[3];
    const float* w3 = (const float*)d_in[4];
    float* y = (float*)d_out;

    reset_kernel<<<1, 32>>>();
    gate_kernel<<<T_TOK / 8, 256>>>(x, wg);
    scan_kernel<<<1, 32>>>();
    build_kernel<<<T_TOK / 256, 256>>>();
    gather_kernel<<<(int)(((size_t)NA * (DIMN / 4) + 255) / 256), 256>>>(x);
    convw_kernel<<<(int)(((size_t)NE * HIDN * DIMN / 4 + 255) / 256), 256>>>(w1, w2, w3);
    ffn1_kernel<<<dim3(HIDN / 64, 128, NE), 256>>>();
    ffn2_kernel<<<dim3(DIMN / 128, 128, NE), 256>>>();
    combine_kernel<<<(T_TOK * DIMN / 4 + 255) / 256, 256>>>(y);
}

// round 5
// speedup vs baseline: 3.2336x; 1.0035x over previous
#include <cuda_runtime.h>
#include <cstdint>
#include <math.h>

#define T_TOK 16384
#define DIMN  1024
#define HIDN  2048
#define NE    8
#define NA    (2*T_TOK)

#define BK    16
#define PADA  20    // row stride (floats) for A / NT-B tiles
#define PADB  136   // row stride (floats) for ffn2 B tile [16][128]

// ============================ helpers ============================
#define CP_ASYNC16(dst, src) asm volatile("cp.async.cg.shared.global [%0], [%1], 16;" :: "r"(dst), "l"(src))
#define CP_COMMIT()          asm volatile("cp.async.commit_group;" ::: "memory")
#define CP_WAIT(n)           asm volatile("cp.async.wait_group %0;" :: "n"(n) : "memory")

__device__ __forceinline__ uint32_t smem_u32(const void* p) {
    uint32_t a;
    asm("{ .reg .u64 t; cvta.to.shared.u64 t, %1; cvt.u32.u64 %0, t; }" : "=r"(a) : "l"(p));
    return a;
}
__device__ __forceinline__ float tf32r(float x) {
    uint32_t u; asm("cvt.rna.tf32.f32 %0, %1;" : "=r"(u) : "f"(x)); return __uint_as_float(u);
}
__device__ __forceinline__ void mma_tf32(float* c, const uint32_t* a, const uint32_t* b) {
    asm volatile(
        "mma.sync.aligned.m16n8k8.row.col.f32.tf32.tf32.f32 "
        "{%0,%1,%2,%3}, {%4,%5,%6,%7}, {%8,%9}, {%0,%1,%2,%3};"
        : "+f"(c[0]), "+f"(c[1]), "+f"(c[2]), "+f"(c[3])
        : "r"(a[0]), "r"(a[1]), "r"(a[2]), "r"(a[3]), "r"(b[0]), "r"(b[1]));
}

// ============================ device scratch ============================
__device__ int   g_count[NE];
__device__ int   g_count2[NE];
__device__ int   g_off[NE];
__device__ int   g_choice[T_TOK * 2];
__device__ float g_cw[T_TOK * 2];
__device__ int   g_tokOf[NA];
__device__ float g_wt[NA];
__device__ int   g_slot[T_TOK * 2];
__device__ float g_Xg[(size_t)NA * DIMN];          // gathered tokens, tf32-rounded
__device__ float g_Ht[(size_t)NA * HIDN];          // hidden, tf32-rounded
__device__ float g_P [(size_t)NA * DIMN];          // per-assignment partials
__device__ float g_w1t[(size_t)NE * HIDN * DIMN];  // tf32-rounded
__device__ float g_w3t[(size_t)NE * HIDN * DIMN];
__device__ float g_w2r[(size_t)NE * HIDN * DIMN];  // tf32-rounded (same layout as w2)

// ============================ small kernels ============================
__global__ void reset_kernel() {
    if (threadIdx.x < NE) { g_count[threadIdx.x] = 0; g_count2[threadIdx.x] = 0; }
}

__global__ void gate_kernel(const float* __restrict__ x, const float* __restrict__ wg) {
    int warp = threadIdx.x >> 5, lane = threadIdx.x & 31;
    int t = blockIdx.x * 8 + warp;
    if (t >= T_TOK) return;
    float acc[NE];
#pragma unroll
    for (int e = 0; e < NE; e++) acc[e] = 0.f;
    const float* xr = x + (size_t)t * DIMN;
    for (int d = lane; d < DIMN; d += 32) {
        float xv = xr[d];
#pragma unroll
        for (int e = 0; e < NE; e++) acc[e] += xv * wg[d * NE + e];
    }
#pragma unroll
    for (int e = 0; e < NE; e++)
#pragma unroll
        for (int o = 16; o > 0; o >>= 1) acc[e] += __shfl_xor_sync(0xffffffffu, acc[e], o);
    if (lane == 0) {
        int i0 = 0; float l0 = acc[0];
#pragma unroll
        for (int e = 1; e < NE; e++) if (acc[e] > l0) { l0 = acc[e]; i0 = e; }
        int i1 = -1; float l1 = -3.0e38f;
#pragma unroll
        for (int e = 0; e < NE; e++) if (e != i0 && acc[e] > l1) { l1 = acc[e]; i1 = e; }
        float w0 = 1.f / (1.f + expf(l1 - l0));
        g_choice[2 * t] = i0;  g_choice[2 * t + 1] = i1;
        g_cw[2 * t] = w0;      g_cw[2 * t + 1] = 1.f - w0;
        atomicAdd(&g_count[i0], 1);
        atomicAdd(&g_count[i1], 1);
    }
}

__global__ void scan_kernel() {
    if (threadIdx.x == 0) {
        int off = 0;
        for (int e = 0; e < NE; e++) { g_off[e] = off; off += g_count[e]; }
    }
}

__global__ void build_kernel() {
    int t = blockIdx.x * blockDim.x + threadIdx.x;
    if (t >= T_TOK) return;
#pragma unroll
    for (int j = 0; j < 2; j++) {
        int e = g_choice[2 * t + j];
        int p = atomicAdd(&g_count2[e], 1);
        int s = g_off[e] + p;
        g_tokOf[s] = t;
        g_wt[s] = g_cw[2 * t + j];
        g_slot[2 * t + j] = s;
    }
}

__global__ void gather_kernel(const float* __restrict__ x) {
    size_t idx = (size_t)blockIdx.x * blockDim.x + threadIdx.x;
    if (idx >= (size_t)NA * (DIMN / 4)) return;
    int row = (int)(idx / (DIMN / 4));
    int c4 = (int)(idx % (DIMN / 4)) * 4;
    int tok = g_tokOf[row];
    float4 v = *reinterpret_cast<const float4*>(&x[(size_t)tok * DIMN + c4]);
    v.x = tf32r(v.x); v.y = tf32r(v.y); v.z = tf32r(v.z); v.w = tf32r(v.w);
    *reinterpret_cast<float4*>(&g_Xg[(size_t)row * DIMN + c4]) = v;
}

__global__ void convw_kernel(const float* __restrict__ w1, const float* __restrict__ w2,
                             const float* __restrict__ w3) {
    size_t idx = (size_t)blockIdx.x * blockDim.x + threadIdx.x;
    if (idx >= (size_t)NE * HIDN * DIMN / 4) return;
    size_t o = idx * 4;
    float4 a = *reinterpret_cast<const float4*>(&w1[o]);
    a.x = tf32r(a.x); a.y = tf32r(a.y); a.z = tf32r(a.z); a.w = tf32r(a.w);
    *reinterpret_cast<float4*>(&g_w1t[o]) = a;
    float4 b = *reinterpret_cast<const float4*>(&w3[o]);
    b.x = tf32r(b.x); b.y = tf32r(b.y); b.z = tf32r(b.z); b.w = tf32r(b.w);
    *reinterpret_cast<float4*>(&g_w3t[o]) = b;
    float4 c = *reinterpret_cast<const float4*>(&w2[o]);
    c.x = tf32r(c.x); c.y = tf32r(c.y); c.z = tf32r(c.z); c.w = tf32r(c.w);
    *reinterpret_cast<float4*>(&g_w2r[o]) = c;
}

// ============================ ffn1: H = silu(Xg W1^T) * (Xg W3^T) ============================
// BM=128 BN=64 BK=16. 256 threads, 8 warps as 4(m) x 2(n); warp tile 32x32.
__global__ void __launch_bounds__(256, 2) ffn1_kernel() {
    int e = blockIdx.z;
    int cnt = g_count[e];
    int mb = blockIdx.y;
    if (mb * 128 >= cnt) return;
    int base = g_off[e] + mb * 128;
    int n0 = blockIdx.x * 64;

    __shared__ float As [2][128 * PADA];
    __shared__ float B1s[2][64 * PADA];
    __shared__ float B3s[2][64 * PADA];

    int tid = threadIdx.x, wid = tid >> 5, lane = tid & 31;
    int wm = wid & 3, wn = wid >> 2;

    // A tile loads: each thread owns 8 contiguous floats of one row:
    // row = tid>>1, col base = (tid&1)*8; two 16B chunks at +0 and +4 floats.
    int arowL = tid >> 1;                   // 0..127
    int acol = (tid & 1) * 8;               // 0 or 8
    int arow = base + arowL; if (arow >= NA) arow = NA - 1;
    const float* srcA = g_Xg + (size_t)arow * DIMN + acol;
    uint32_t dstA = smem_u32(&As[0][arowL * PADA + acol]);

    int browL = tid >> 2;                   // 0..63
    int bcol = (tid & 3) * 4;               // 0,4,8,12
    const float* srcB1 = g_w1t + ((size_t)e * HIDN + n0 + browL) * DIMN + bcol;
    const float* srcB3 = g_w3t + ((size_t)e * HIDN + n0 + browL) * DIMN + bcol;
    uint32_t dstB1 = smem_u32(&B1s[0][browL * PADA + bcol]);
    uint32_t dstB3 = smem_u32(&B3s[0][browL * PADA + bcol]);

    const uint32_t stA  = (uint32_t)(128 * PADA * 4);
    const uint32_t stB  = (uint32_t)(64 * PADA * 4);

    float acc1[2][4][4], acc3[2][4][4];
#pragma unroll
    for (int i = 0; i < 2; i++)
#pragma unroll
        for (int j = 0; j < 4; j++)
#pragma unroll
            for (int v = 0; v < 4; v++) { acc1[i][j][v] = 0.f; acc3[i][j][v] = 0.f; }

    // prefetch stage 0
    {
        CP_ASYNC16(dstA, srcA); CP_ASYNC16(dstA + 16, srcA + 4);
        CP_ASYNC16(dstB1, srcB1); CP_ASYNC16(dstB3, srcB3);
        CP_COMMIT();
    }

    const int KT = DIMN / BK;   // 64
    for (int kt = 0; kt < KT; kt++) {
        int cur = kt & 1;
        if (kt + 1 < KT) {
            int nx = (kt + 1) & 1;
            const float* sA = srcA + (kt + 1) * BK;
            const float* s1 = srcB1 + (kt + 1) * BK;
            const float* s3 = srcB3 + (kt + 1) * BK;
            CP_ASYNC16(dstA + nx * stA, sA); CP_ASYNC16(dstA + nx * stA + 16, sA + 4);
            CP_ASYNC16(dstB1 + nx * stB, s1); CP_ASYNC16(dstB3 + nx * stB, s3);
            CP_COMMIT();
            CP_WAIT(1);
        } else {
            CP_WAIT(0);
        }
        __syncthreads();

        const float* A = As[cur];
        const float* B1 = B1s[cur];
        const float* B3 = B3s[cur];
#pragma unroll
        for (int kk = 0; kk < 2; kk++) {
            int k0 = kk * 8;
            uint32_t a[2][4];
#pragma unroll
            for (int i = 0; i < 2; i++) {
                int r = wm * 32 + i * 16 + (lane >> 2);
                int c = k0 + (lane & 3);
                a[i][0] = __float_as_uint(A[r * PADA + c]);
                a[i][1] = __float_as_uint(A[(r + 8) * PADA + c]);
                a[i][2] = __float_as_uint(A[r * PADA + c + 4]);
                a[i][3] = __float_as_uint(A[(r + 8) * PADA + c + 4]);
            }
            uint32_t b1[4][2], b3[4][2];
#pragma unroll
            for (int j = 0; j < 4; j++) {
                int n = wn * 32 + j * 8 + (lane >> 2);
                int c = k0 + (lane & 3);
                b1[j][0] = __float_as_uint(B1[n * PADA + c]);
                b1[j][1] = __float_as_uint(B1[n * PADA + c + 4]);
                b3[j][0] = __float_as_uint(B3[n * PADA + c]);
                b3[j][1] = __float_as_uint(B3[n * PADA + c + 4]);
            }
#pragma unroll
            for (int i = 0; i < 2; i++)
#pragma unroll
                for (int j = 0; j < 4; j++) {
                    mma_tf32(acc1[i][j], a[i], b1[j]);
                    mma_tf32(acc3[i][j], a[i], b3[j]);
                }
        }
        __syncthreads();
    }

    // epilogue: h = silu(z1)*z3, tf32-round, store
#pragma unroll
    for (int i = 0; i < 2; i++) {
#pragma unroll
        for (int half = 0; half < 2; half++) {
            int rloc = wm * 32 + i * 16 + (lane >> 2) + half * 8;
            if (mb * 128 + rloc < cnt) {
                float* hrow = g_Ht + (size_t)(base + rloc) * HIDN + n0;
#pragma unroll
                for (int j = 0; j < 4; j++) {
                    int cl = wn * 32 + j * 8 + (lane & 3) * 2;
                    float z0 = acc1[i][j][half * 2 + 0];
                    float z1 = acc1[i][j][half * 2 + 1];
                    float h0 = tf32r(z0 / (1.f + __expf(-z0)) * acc3[i][j][half * 2 + 0]);
                    float h1 = tf32r(z1 / (1.f + __expf(-z1)) * acc3[i][j][half * 2 + 1]);
                    *reinterpret_cast<float2*>(&hrow[cl]) = make_float2(h0, h1);
                }
            }
        }
    }
}

// ============================ ffn2: P = H W2 ============================
// BM=128 BN=128 BK=16. 256 threads, 8 warps as 4(m) x 2(n); warp tile 32x64.
__global__ void __launch_bounds__(256, 2) ffn2_kernel() {
    int e = blockIdx.z;
    int cnt = g_count[e];
    int mb = blockIdx.y;
    if (mb * 128 >= cnt) return;
    int base = g_off[e] + mb * 128;
    int n0 = blockIdx.x * 128;

    __shared__ float As[2][128 * PADA];
    __shared__ float Bs[2][16 * PADB];

    int tid = threadIdx.x, wid = tid >> 5, lane = tid & 31;
    int wm = wid & 3, wn = wid >> 2;

    int arowL = tid >> 1;
    int acol = (tid & 1) * 8;
    int arow = base + arowL; if (arow >= NA) arow = NA - 1;
    const float* srcA = g_Ht + (size_t)arow * HIDN + acol;
    uint32_t dstA = smem_u32(&As[0][arowL * PADA + acol]);

    // B: 16 rows x 128 floats; tid -> row=tid>>4 (0..15), col base=(tid&15)*8
    int browL = tid >> 4;
    int bcol = (tid & 15) * 8;
    const float* srcB = g_w2r + ((size_t)e * HIDN + browL) * DIMN + n0 + bcol;
    uint32_t dstB = smem_u32(&Bs[0][browL * PADB + bcol]);

    const uint32_t stA = (uint32_t)(128 * PADA * 4);
    const uint32_t stB = (uint32_t)(16 * PADB * 4);

    float acc[2][8][4];
#pragma unroll
    for (int i = 0; i < 2; i++)
#pragma unroll
        for (int j = 0; j < 8; j++)
#pragma unroll
            for (int v = 0; v < 4; v++) acc[i][j][v] = 0.f;

    {
        CP_ASYNC16(dstA, srcA); CP_ASYNC16(dstA + 16, srcA + 4);
        CP_ASYNC16(dstB, srcB); CP_ASYNC16(dstB + 16, srcB + 4);
        CP_COMMIT();
    }

    const int KT = HIDN / BK;   // 128
    for (int kt = 0; kt < KT; kt++) {
        int cur = kt & 1;
        if (kt + 1 < KT) {
            int nx = (kt + 1) & 1;
            const float* sA = srcA + (kt + 1) * BK;
            const float* sB = srcB + (size_t)(kt + 1) * BK * DIMN;
            CP_ASYNC16(dstA + nx * stA, sA); CP_ASYNC16(dstA + nx * stA + 16, sA + 4);
            CP_ASYNC16(dstB + nx * stB, sB); CP_ASYNC16(dstB + nx * stB + 16, sB + 4);
            CP_COMMIT();
            CP_WAIT(1);
        } else {
            CP_WAIT(0);
        }
        __syncthreads();

        const float* A = As[cur];
        const float* B = Bs[cur];
#pragma unroll
        for (int kk = 0; kk < 2; kk++) {
            int k0 = kk * 8;
            uint32_t a[2][4];
#pragma unroll
            for (int i = 0; i < 2; i++) {
                int r = wm * 32 + i * 16 + (lane >> 2);
                int c = k0 + (lane & 3);
                a[i][0] = __float_as_uint(A[r * PADA + c]);
                a[i][1] = __float_as_uint(A[(r + 8) * PADA + c]);
                a[i][2] = __float_as_uint(A[r * PADA + c + 4]);
                a[i][3] = __float_as_uint(A[(r + 8) * PADA + c + 4]);
            }
            uint32_t b[8][2];
#pragma unroll
            for (int j = 0; j < 8; j++) {
                int n = wn * 64 + j * 8 + (lane >> 2);
                int k = k0 + (lane & 3);
                b[j][0] = __float_as_uint(B[k * PADB + n]);
                b[j][1] = __float_as_uint(B[(k + 4) * PADB + n]);
            }
#pragma unroll
            for (int i = 0; i < 2; i++)
#pragma unroll
                for (int j = 0; j < 8; j++)
                    mma_tf32(acc[i][j], a[i], b[j]);
        }
        __syncthreads();
    }

#pragma unroll
    for (int i = 0; i < 2; i++) {
#pragma unroll
        for (int half = 0; half < 2; half++) {
            int rloc = wm * 32 + i * 16 + (lane >> 2) + half * 8;
            if (mb * 128 + rloc < cnt) {
                float* prow = g_P + (size_t)(base + rloc) * DIMN + n0;
#pragma unroll
                for (int j = 0; j < 8; j++) {
                    int cl = wn * 64 + j * 8 + (lane & 3) * 2;
                    *reinterpret_cast<float2*>(&prow[cl]) =
                        make_float2(acc[i][j][half * 2 + 0], acc[i][j][half * 2 + 1]);
                }
            }
        }
    }
}

// ============================ combine ============================
__global__ void combine_kernel(float* __restrict__ y) {
    size_t idx = (size_t)blockIdx.x * blockDim.x + threadIdx.x;
    if (idx >= (size_t)T_TOK * DIMN / 4) return;
    int t = (int)(idx / (DIMN / 4));
    int d4 = (int)(idx % (DIMN / 4)) * 4;
    int s0 = g_slot[2 * t], s1 = g_slot[2 * t + 1];
    float w0 = g_wt[s0], w1 = g_wt[s1];
    float4 p0 = *reinterpret_cast<const float4*>(&g_P[(size_t)s0 * DIMN + d4]);
    float4 p1 = *reinterpret_cast<const float4*>(&g_P[(size_t)s1 * DIMN + d4]);
    float4 r;
    r.x = w0 * p0.x + w1 * p1.x;
    r.y = w0 * p0.y + w1 * p1.y;
    r.z = w0 * p0.z + w1 * p1.z;
    r.w = w0 * p0.w + w1 * p1.w;
    *reinterpret_cast<float4*>(&y[(size_t)t * DIMN + d4]) = r;
}

// ============================ launch ============================
extern "C" void kernel_launch(void* const* d_in, const int* in_sizes, int n_in,
                              void* d_out, int out_size) {
    const float* x  = (const float*)d_in[0];
    const float* wg = (const float*)d_in[1];
    const float* w1 = (const float*)d_in[2];
    const float* w2 = (const float*)d_in[3];
    const float* w3 = (const float*)d_in[4];
    float* y = (float*)d_out;

    reset_kernel<<<1, 32>>>();
    gate_kernel<<<T_TOK / 8, 256>>>(x, wg);
    scan_kernel<<<1, 32>>>();
    build_kernel<<<T_TOK / 256, 256>>>();
    gather_kernel<<<(int)(((size_t)NA * (DIMN / 4) + 255) / 256), 256>>>(x);
    convw_kernel<<<(int)(((size_t)NE * HIDN * DIMN / 4 + 255) / 256), 256>>>(w1, w2, w3);
    ffn1_kernel<<<dim3(HIDN / 64, 128, NE), 256>>>();
    ffn2_kernel<<<dim3(DIMN / 128, 128, NE), 256>>>();
    combine_kernel<<<(T_TOK * DIMN / 4 + 255) / 256, 256>>>(y);
}